// round 8
// baseline (speedup 1.0000x reference)
#include <cuda_runtime.h>

#define N_FFT    800
#define HOP      200
#define BATCH    32
#define TLEN     480000
#define PAD      400
#define N_FRAMES 2401                 // (480800 - 800)/200 + 1
#define TS       8000                 // output tile per block
#define NF_LOC   (TS / HOP + 3)       // 43 frame positions per tile
#define NBLK     (TS / HOP + 6)       // 46 hop blocks feed those frames
#define SPAN     (TS + 1200)          // staged input: [t0-600, t0+TS+600)

#define PI_D 3.14159265358979323846

// Fully fused STFT->mag/phase->iSTFT (linear-collapse derivation, R3/R6).
//   Hann identities: win(r+400)=1-win(r), win(r+600)=1-win(r+200),
//   sum_j win(r+200j)^2 = 1.5 exactly.
//   Per hop block g: X=sum(x), A=sum(win(r)x), B=sum(win(r+200)x) (per parity).
//   S[f] = A[f] + B[f+1] + (X[f+2]-A[f+2]) + (X[f+3]-B[f+3]).
//   out = 0.75*x + (C0 + win(r)*C1 + win(r+200)*C2)/800,
//     C0=S[q-2]+S[q-3], C1=S[q]-S[q-2], C2=S[q-1]-S[q-3]  (per parity).
//   Boundary (missing frame j at edge): out -= 0.5*x*win(r+200j)^2, S:=0.
__global__ __launch_bounds__(1024, 2)
void stft_fused_kernel(const float* __restrict__ x, float* __restrict__ out) {
    __shared__ __align__(16) float sx[SPAN];        // staged (clamped) input
    __shared__ __align__(16) float sw[N_FFT];       // Hann window
    __shared__ float sX[NBLK][2], sA[NBLK][2], sB[NBLK][2];
    __shared__ __align__(16) float sC[NF_LOC][8];   // packed {C0e,C0o,C1e,C1o,C2e,C2o,-,-}

    const int b   = blockIdx.y;
    const int t0  = blockIdx.x * TS;
    const float* xb = x + (size_t)b * TLEN;
    const int base = t0 - 600;
    const bool eFirst = (blockIdx.x == 0);
    const bool eLast  = (blockIdx.x == gridDim.x - 1);
    const int tid = threadIdx.x;

    // Window table.
    for (int i = tid; i < N_FFT; i += blockDim.x)
        sw[i] = 0.5f - 0.5f * cosf((float)i * (float)(2.0 * PI_D / N_FFT));

    // Stage input (interior: base multiple of 4 -> float4 path).
    if (!(eFirst | eLast)) {
        const float4* __restrict__ src = (const float4*)(xb + base);
        float4* dst = (float4*)sx;
        for (int i = tid; i < SPAN / 4; i += blockDim.x)
            dst[i] = src[i];
    } else {
        for (int i = tid; i < SPAN; i += blockDim.x) {
            int idx = base + i;
            idx = idx < 0 ? 0 : (idx >= TLEN ? TLEN - 1 : idx);
            sx[i] = xb[idx];
        }
    }
    __syncthreads();

    // Phase 1: per hop block, three parity sums via float4 loads.
    // Chunk c covers elements 4c..4c+3 (parities e,o,e,o). 50 chunks/block.
    const int w = tid >> 5;
    const int l = tid & 31;
    const float4* __restrict__ sw4 = (const float4*)sw;
    for (int gl = w; gl < NBLK; gl += 32) {
        const float4* __restrict__ sx4g = (const float4*)&sx[gl * HOP];
        float xe = 0.f, xo = 0.f, ae = 0.f, ao = 0.f, be = 0.f, bo = 0.f;
        #pragma unroll
        for (int k = 0; k < 2; k++) {
            const int c = l + 32 * k;
            if (c < HOP / 4) {
                const float4 v  = sx4g[c];
                const float4 wa = sw4[c];
                const float4 wb = sw4[c + HOP / 4];
                xe += v.x + v.z;                   xo += v.y + v.w;
                ae = fmaf(wa.x, v.x, fmaf(wa.z, v.z, ae));
                ao = fmaf(wa.y, v.y, fmaf(wa.w, v.w, ao));
                be = fmaf(wb.x, v.x, fmaf(wb.z, v.z, be));
                bo = fmaf(wb.y, v.y, fmaf(wb.w, v.w, bo));
            }
        }
        #pragma unroll
        for (int d = 16; d >= 1; d >>= 1) {
            xe += __shfl_xor_sync(0xffffffffu, xe, d);
            xo += __shfl_xor_sync(0xffffffffu, xo, d);
            ae += __shfl_xor_sync(0xffffffffu, ae, d);
            ao += __shfl_xor_sync(0xffffffffu, ao, d);
            be += __shfl_xor_sync(0xffffffffu, be, d);
            bo += __shfl_xor_sync(0xffffffffu, bo, d);
        }
        if (l == 0) {
            sX[gl][0] = xe; sX[gl][1] = xo;
            sA[gl][0] = ae; sA[gl][1] = ao;
            sB[gl][0] = be; sB[gl][1] = bo;
        }
    }
    __syncthreads();

    // Phase 1.5: packed per-frame-position combos (invalid frames -> S=0).
    const int f_base = t0 / HOP - 1;
    if (tid < 80) {                                // flq in [3, 43)
        const int flq = 3 + (tid >> 1), par = tid & 1;
        float s[4];                                // s[j] = S(flq - j)
        #pragma unroll
        for (int j = 0; j < 4; j++) {
            const int fl = flq - j;
            const int fg = fl + f_base;
            float v = sA[fl][par] + sB[fl + 1][par]
                    + (sX[fl + 2][par] - sA[fl + 2][par])
                    + (sX[fl + 3][par] - sB[fl + 3][par]);
            s[j] = (fg < 0 || fg >= N_FRAMES) ? 0.0f : v;
        }
        sC[flq][0 + par] = s[2] + s[3];            // C0
        sC[flq][2 + par] = s[0] - s[2];            // C1
        sC[flq][4 + par] = s[1] - s[3];            // C2
    }
    __syncthreads();

    // Phase 2: synthesis, 4 outputs per iteration, all-vector.
    float* __restrict__ ob = out + (size_t)b * TLEN + t0;
    const float4* __restrict__ sx4 = (const float4*)sx;
    for (int v = tid; v < TS / 4; v += blockDim.x) {
        const int u   = v + 100;                   // (4v + PAD)/4
        const int g   = u / 50;                    // q = t0/HOP + g
        const int r4  = u - g * 50;                // r0 = 4*r4
        const int flq = g + 1;
        const float4 xv = sx4[v + 150];
        const float4 w0 = sw4[r4];
        const float4 w1 = sw4[r4 + 50];
        const float4 cA = *(const float4*)&sC[flq][0];   // C0e,C0o,C1e,C1o
        const float4 cB = *(const float4*)&sC[flq][4];   // C2e,C2o,-,-
        float4 o;   // parities: x,z even; y,w odd
        o.x = fmaf(0.75f, xv.x, fmaf(w1.x, cB.x, fmaf(w0.x, cA.z, cA.x)) * (1.0f / 800.0f));
        o.y = fmaf(0.75f, xv.y, fmaf(w1.y, cB.y, fmaf(w0.y, cA.w, cA.y)) * (1.0f / 800.0f));
        o.z = fmaf(0.75f, xv.z, fmaf(w1.z, cB.x, fmaf(w0.z, cA.z, cA.x)) * (1.0f / 800.0f));
        o.w = fmaf(0.75f, xv.w, fmaf(w1.w, cB.y, fmaf(w0.w, cA.w, cA.y)) * (1.0f / 800.0f));
        // Boundary wsq correction (only first/last 50 quads of edge tiles):
        // missing frame j=3 at signal start (window r+600), j=0 at end (window r).
        if (eFirst && v < 50) {
            const float4 w3 = sw4[r4 + 150];
            o.x = fmaf(-0.5f * w3.x * w3.x, xv.x, o.x);
            o.y = fmaf(-0.5f * w3.y * w3.y, xv.y, o.y);
            o.z = fmaf(-0.5f * w3.z * w3.z, xv.z, o.z);
            o.w = fmaf(-0.5f * w3.w * w3.w, xv.w, o.w);
        }
        if (eLast && v >= TS / 4 - 50) {
            o.x = fmaf(-0.5f * w0.x * w0.x, xv.x, o.x);
            o.y = fmaf(-0.5f * w0.y * w0.y, xv.y, o.y);
            o.z = fmaf(-0.5f * w0.z * w0.z, xv.z, o.z);
            o.w = fmaf(-0.5f * w0.w * w0.w, xv.w, o.w);
        }
        *(float4*)&ob[4 * v] = o;
    }
}

extern "C" void kernel_launch(void* const* d_in, const int* in_sizes, int n_in,
                              void* d_out, int out_size) {
    const float* x = (const float*)d_in[0];
    float* out = (float*)d_out;

    dim3 grid(TLEN / TS, BATCH);       // 60 x 32 = 1920 blocks
    stft_fused_kernel<<<grid, 1024>>>(x, out);
}

// round 9
// speedup vs baseline: 1.1565x; 1.1565x over previous
#include <cuda_runtime.h>

#define N_FFT    800
#define HOP      200
#define BATCH    32
#define TLEN     480000
#define PAD      400
#define N_FRAMES 2401                 // (480800 - 800)/200 + 1
#define TS       8000                 // output tile per block
#define NF_LOC   (TS / HOP + 3)       // 43 frame positions per tile
#define NBLK     (TS / HOP + 6)       // 46 hop blocks feed those frames
#define SPAN     (TS + 1200)          // staged input: [t0-600, t0+TS+600)
#define SPAN_PAD (SPAN + 400)         // padding so dummy phase-1 lanes stay in-bounds

#define PI_D 3.14159265358979323846

// Fully fused STFT->mag/phase->iSTFT (linear-collapse derivation, R3/R6).
//   Hann identities: win(r+400)=1-win(r), win(r+600)=1-win(r+200),
//   sum_j win(r+200j)^2 = 1.5 exactly.
//   Per hop block g: X=sum(x), A=sum(win(r)x), B=sum(win(r+200)x) (per parity).
//   S[f] = A[f] + B[f+1] + (X[f+2]-A[f+2]) + (X[f+3]-B[f+3]).
//   out = 0.75*x + (C0 + win(r)*C1 + win(r+200)*C2)/800,
//     C0=S[q-2]+S[q-3], C1=S[q]-S[q-2], C2=S[q-1]-S[q-3]  (per parity).
//   Boundary (missing frame j at edge): out -= 0.5*x*win(r+200j)^2, S:=0.
__global__ __launch_bounds__(1024, 2)
void stft_fused_kernel(const float* __restrict__ x, float* __restrict__ out) {
    __shared__ __align__(16) float sx[SPAN_PAD];    // staged (clamped) input
    __shared__ __align__(16) float sw[N_FFT];       // Hann window
    __shared__ float sX[NBLK][2], sA[NBLK][2], sB[NBLK][2];
    __shared__ __align__(16) float sC[NF_LOC][8];   // {C0e,C0o,C1e,C1o,C2e,C2o,-,-}

    const int b   = blockIdx.y;
    const int t0  = blockIdx.x * TS;
    const float* xb = x + (size_t)b * TLEN;
    const int base = t0 - 600;
    const bool eFirst = (blockIdx.x == 0);
    const bool eLast  = (blockIdx.x == gridDim.x - 1);
    const int tid = threadIdx.x;

    // Window table.
    for (int i = tid; i < N_FFT; i += blockDim.x)
        sw[i] = 0.5f - 0.5f * cosf((float)i * (float)(2.0 * PI_D / N_FFT));

    // Stage input (interior: base multiple of 4 -> float4 path).
    if (!(eFirst | eLast)) {
        const float4* __restrict__ src = (const float4*)(xb + base);
        float4* dst = (float4*)sx;
        for (int i = tid; i < SPAN / 4; i += blockDim.x)
            dst[i] = src[i];
    } else {
        for (int i = tid; i < SPAN; i += blockDim.x) {
            int idx = base + i;
            idx = idx < 0 ? 0 : (idx >= TLEN ? TLEN - 1 : idx);
            sx[i] = xb[idx];
        }
    }
    // Zero the padding tail so dummy phase-1 lanes read finite values.
    for (int i = SPAN + tid; i < SPAN_PAD; i += blockDim.x) sx[i] = 0.0f;
    __syncthreads();

    // Phase 1: per hop block, three parity sums. Two threads per hop block,
    // each owning 25 consecutive float4s (100 samples) -> sequential register
    // accumulation, single pair-combine shuffle, no warp butterfly.
    // Bank check: lane t reads word 100*t + 4*c; stride 100 == 4 (mod 32)
    // banks -> distinct 4-word groups per lane -> conflict-free LDS.128.
    const float4* __restrict__ sw4 = (const float4*)sw;
    if (tid < 96) {                                 // 92 real + 4 dummy lanes
        const int g = tid >> 1, h = tid & 1;
        const float4* __restrict__ xs = (const float4*)sx + g * (HOP / 4) + h * 25;
        const float4* __restrict__ wsa = sw4 + h * 25;
        float xe = 0.f, xo = 0.f, ae = 0.f, ao = 0.f, be = 0.f, bo = 0.f;
        #pragma unroll 5
        for (int c = 0; c < 25; c++) {
            const float4 v  = xs[c];
            const float4 wa = wsa[c];
            const float4 wb = wsa[c + 50];
            xe += v.x + v.z;                   xo += v.y + v.w;
            ae = fmaf(wa.x, v.x, fmaf(wa.z, v.z, ae));
            ao = fmaf(wa.y, v.y, fmaf(wa.w, v.w, ao));
            be = fmaf(wb.x, v.x, fmaf(wb.z, v.z, be));
            bo = fmaf(wb.y, v.y, fmaf(wb.w, v.w, bo));
        }
        xe += __shfl_xor_sync(0xffffffffu, xe, 1);
        xo += __shfl_xor_sync(0xffffffffu, xo, 1);
        ae += __shfl_xor_sync(0xffffffffu, ae, 1);
        ao += __shfl_xor_sync(0xffffffffu, ao, 1);
        be += __shfl_xor_sync(0xffffffffu, be, 1);
        bo += __shfl_xor_sync(0xffffffffu, bo, 1);
        if (!h && g < NBLK) {
            sX[g][0] = xe; sX[g][1] = xo;
            sA[g][0] = ae; sA[g][1] = ao;
            sB[g][0] = be; sB[g][1] = bo;
        }
    }
    __syncthreads();

    // Phase 1.5: packed per-frame-position combos (invalid frames -> S=0).
    const int f_base = t0 / HOP - 1;
    if (tid < 80) {                                // flq in [3, 43)
        const int flq = 3 + (tid >> 1), par = tid & 1;
        float s[4];                                // s[j] = S(flq - j)
        #pragma unroll
        for (int j = 0; j < 4; j++) {
            const int fl = flq - j;
            const int fg = fl + f_base;
            float v = sA[fl][par] + sB[fl + 1][par]
                    + (sX[fl + 2][par] - sA[fl + 2][par])
                    + (sX[fl + 3][par] - sB[fl + 3][par]);
            s[j] = (fg < 0 || fg >= N_FRAMES) ? 0.0f : v;
        }
        sC[flq][0 + par] = s[2] + s[3];            // C0
        sC[flq][2 + par] = s[0] - s[2];            // C1
        sC[flq][4 + par] = s[1] - s[3];            // C2
    }
    __syncthreads();

    // Phase 2: synthesis, 4 outputs per iteration, all-vector.
    float* __restrict__ ob = out + (size_t)b * TLEN + t0;
    const float4* __restrict__ sx4 = (const float4*)sx;
    for (int v = tid; v < TS / 4; v += blockDim.x) {
        const int u   = v + 100;                   // (4v + PAD)/4
        const int g   = u / 50;                    // q = t0/HOP + g
        const int r4  = u - g * 50;                // r0 = 4*r4
        const int flq = g + 1;
        const float4 xv = sx4[v + 150];
        const float4 w0 = sw4[r4];
        const float4 w1 = sw4[r4 + 50];
        const float4 cA = *(const float4*)&sC[flq][0];   // C0e,C0o,C1e,C1o
        const float4 cB = *(const float4*)&sC[flq][4];   // C2e,C2o,-,-
        float4 o;   // parities: x,z even; y,w odd
        o.x = fmaf(0.75f, xv.x, fmaf(w1.x, cB.x, fmaf(w0.x, cA.z, cA.x)) * (1.0f / 800.0f));
        o.y = fmaf(0.75f, xv.y, fmaf(w1.y, cB.y, fmaf(w0.y, cA.w, cA.y)) * (1.0f / 800.0f));
        o.z = fmaf(0.75f, xv.z, fmaf(w1.z, cB.x, fmaf(w0.z, cA.z, cA.x)) * (1.0f / 800.0f));
        o.w = fmaf(0.75f, xv.w, fmaf(w1.w, cB.y, fmaf(w0.w, cA.w, cA.y)) * (1.0f / 800.0f));
        // Boundary wsq correction (first/last 50 quads of edge tiles only):
        // missing frame j=3 at signal start (window r+600), j=0 at end (window r).
        if (eFirst && v < 50) {
            const float4 w3 = sw4[r4 + 150];
            o.x = fmaf(-0.5f * w3.x * w3.x, xv.x, o.x);
            o.y = fmaf(-0.5f * w3.y * w3.y, xv.y, o.y);
            o.z = fmaf(-0.5f * w3.z * w3.z, xv.z, o.z);
            o.w = fmaf(-0.5f * w3.w * w3.w, xv.w, o.w);
        }
        if (eLast && v >= TS / 4 - 50) {
            o.x = fmaf(-0.5f * w0.x * w0.x, xv.x, o.x);
            o.y = fmaf(-0.5f * w0.y * w0.y, xv.y, o.y);
            o.z = fmaf(-0.5f * w0.z * w0.z, xv.z, o.z);
            o.w = fmaf(-0.5f * w0.w * w0.w, xv.w, o.w);
        }
        *(float4*)&ob[4 * v] = o;
    }
}

extern "C" void kernel_launch(void* const* d_in, const int* in_sizes, int n_in,
                              void* d_out, int out_size) {
    const float* x = (const float*)d_in[0];
    float* out = (float*)d_out;

    dim3 grid(TLEN / TS, BATCH);       // 60 x 32 = 1920 blocks
    stft_fused_kernel<<<grid, 1024>>>(x, out);
}